// round 13
// baseline (speedup 1.0000x reference)
#include <cuda_runtime.h>
#include <cstdint>
#include <math.h>

#define B_  4
#define S_  2048
#define D_  1024
#define H_  16
#define HD_ 64
#define M_  (B_ * S_)   // 8192

// Scratch for Q,K,V in [b,h,s,hd] layout (32 MB each)
__device__ float g_q[B_ * H_ * S_ * HD_];
__device__ float g_k[B_ * H_ * S_ * HD_];
__device__ float g_v[B_ * H_ * S_ * HD_];

// ---------------------------------------------------------------------------
// tf32 warp MMA helpers (portable PTX, works on compute_103)
// ---------------------------------------------------------------------------
__device__ __forceinline__ uint32_t f2tf32(float x) {
    uint32_t r;
    asm("cvt.rna.tf32.f32 %0, %1;" : "=r"(r) : "f"(x));
    return r;
}
__device__ __forceinline__ float ex2f(float x) {
    float y;
    asm("ex2.approx.f32 %0, %1;" : "=f"(y) : "f"(x));
    return y;
}
__device__ __forceinline__ void mma_tf32(float d[4], const uint32_t a[4],
                                         const uint32_t b[2], const float c[4]) {
    asm volatile(
        "mma.sync.aligned.m16n8k8.row.col.f32.tf32.tf32.f32 "
        "{%0,%1,%2,%3}, {%4,%5,%6,%7}, {%8,%9}, {%10,%11,%12,%13};"
        : "=f"(d[0]), "=f"(d[1]), "=f"(d[2]), "=f"(d[3])
        : "r"(a[0]), "r"(a[1]), "r"(a[2]), "r"(a[3]),
          "r"(b[0]), "r"(b[1]),
          "f"(c[0]), "f"(c[1]), "f"(c[2]), "f"(c[3]));
}

// ===========================================================================
// Kernel 1: QKV projection via tf32 mma.sync, double-buffered (unchanged R9).
// ===========================================================================
#define QLA 36
#define QSTG (2 * 128 * QLA)
#define QKV_SMEM ((size_t)2 * QSTG * 4)

__global__ __launch_bounds__(256, 2) void qkv_mma_kernel(
    const float* __restrict__ x,
    const float* __restrict__ Wq, const float* __restrict__ bq,
    const float* __restrict__ Wk, const float* __restrict__ bk,
    const float* __restrict__ Wv, const float* __restrict__ bv)
{
    extern __shared__ uint32_t smq[];

    const int tid  = threadIdx.x;
    const int lane = tid & 31;
    const int wid  = tid >> 5;
    const int qr = lane >> 2;
    const int qc = lane & 3;

    const int bx = blockIdx.x;
    const int z  = bx >> 3;
    const int n0 = (bx & 7) * 128;
    const int m0 = blockIdx.y * 128;

    const float* W    = (z == 0) ? Wq : (z == 1) ? Wk : Wv;
    const float* bias = (z == 0) ? bq : (z == 1) ? bk : bv;
    float*       out  = (z == 0) ? g_q : (z == 1) ? g_k : g_v;

    const int warpM = (wid >> 1) * 32;       // 0,32,64,96
    const int warpN = (wid & 1) * 64;        // 0,64

    const int lr = tid >> 3;                 // loader row 0..31 (x4 via i)
    const int lc = (tid & 7) << 2;           // loader col 0,4..28

    float acc[2][8][4];
    #pragma unroll
    for (int mt = 0; mt < 2; ++mt)
        #pragma unroll
        for (int nt = 0; nt < 8; ++nt)
            #pragma unroll
            for (int i = 0; i < 4; ++i) acc[mt][nt][i] = 0.f;

    float4 pa[4], pb[4];
    #pragma unroll
    for (int i = 0; i < 4; ++i) {
        int r = lr + i * 32;
        pa[i] = *reinterpret_cast<const float4*>(&x[(size_t)(m0 + r) * D_ + lc]);
        pb[i] = *reinterpret_cast<const float4*>(&W[(size_t)(n0 + r) * D_ + lc]);
    }
    {
        uint32_t* A = smq;
        uint32_t* Bp = smq + 128 * QLA;
        #pragma unroll
        for (int i = 0; i < 4; ++i) {
            int r = lr + i * 32;
            uint4 ta = make_uint4(f2tf32(pa[i].x), f2tf32(pa[i].y),
                                  f2tf32(pa[i].z), f2tf32(pa[i].w));
            *reinterpret_cast<uint4*>(&A[r * QLA + lc]) = ta;
            uint4 tb = make_uint4(f2tf32(pb[i].x), f2tf32(pb[i].y),
                                  f2tf32(pb[i].z), f2tf32(pb[i].w));
            *reinterpret_cast<uint4*>(&Bp[r * QLA + lc]) = tb;
        }
    }
    __syncthreads();

    for (int kc = 0; kc < 32; ++kc) {
        const int s = kc & 1;
        if (kc + 1 < 32) {
            int koff = (kc + 1) * 32;
            #pragma unroll
            for (int i = 0; i < 4; ++i) {
                int r = lr + i * 32;
                pa[i] = *reinterpret_cast<const float4*>(
                    &x[(size_t)(m0 + r) * D_ + koff + lc]);
                pb[i] = *reinterpret_cast<const float4*>(
                    &W[(size_t)(n0 + r) * D_ + koff + lc]);
            }
        }

        const uint32_t* As = smq + s * QSTG;
        const uint32_t* Bs = As + 128 * QLA;
        #pragma unroll
        for (int k8 = 0; k8 < 4; ++k8) {
            int k0 = k8 * 8;
            uint32_t a[2][4];
            #pragma unroll
            for (int mt = 0; mt < 2; ++mt) {
                int r = warpM + mt * 16 + qr;
                a[mt][0] = As[r * QLA + k0 + qc];
                a[mt][1] = As[(r + 8) * QLA + k0 + qc];
                a[mt][2] = As[r * QLA + k0 + qc + 4];
                a[mt][3] = As[(r + 8) * QLA + k0 + qc + 4];
            }
            #pragma unroll
            for (int nt = 0; nt < 8; ++nt) {
                uint32_t b[2];
                int n = warpN + nt * 8 + qr;
                b[0] = Bs[n * QLA + k0 + qc];
                b[1] = Bs[n * QLA + k0 + qc + 4];
                mma_tf32(acc[0][nt], a[0], b, acc[0][nt]);
                mma_tf32(acc[1][nt], a[1], b, acc[1][nt]);
            }
        }

        if (kc + 1 < 32) {
            uint32_t* A = smq + (s ^ 1) * QSTG;
            uint32_t* Bp = A + 128 * QLA;
            #pragma unroll
            for (int i = 0; i < 4; ++i) {
                int r = lr + i * 32;
                uint4 ta = make_uint4(f2tf32(pa[i].x), f2tf32(pa[i].y),
                                      f2tf32(pa[i].z), f2tf32(pa[i].w));
                *reinterpret_cast<uint4*>(&A[r * QLA + lc]) = ta;
                uint4 tb = make_uint4(f2tf32(pb[i].x), f2tf32(pb[i].y),
                                      f2tf32(pb[i].z), f2tf32(pb[i].w));
                *reinterpret_cast<uint4*>(&Bp[r * QLA + lc]) = tb;
            }
        }
        __syncthreads();
    }

    #pragma unroll
    for (int mt = 0; mt < 2; ++mt) {
        #pragma unroll
        for (int nt = 0; nt < 8; ++nt) {
            int gn = n0 + warpN + nt * 8 + 2 * qc;   // even
            int head = gn >> 6;
            int hd = gn & 63;
            float b0 = bias[gn], b1 = bias[gn + 1];
            int rA = m0 + warpM + mt * 16 + qr;
            int rB = rA + 8;
            int bbA = rA >> 11, ssA = rA & (S_ - 1);
            int bbB = rB >> 11, ssB = rB & (S_ - 1);
            float2 vA = make_float2(acc[mt][nt][0] + b0, acc[mt][nt][1] + b1);
            float2 vB = make_float2(acc[mt][nt][2] + b0, acc[mt][nt][3] + b1);
            *reinterpret_cast<float2*>(
                &out[(((size_t)bbA * H_ + head) * S_ + ssA) * HD_ + hd]) = vA;
            *reinterpret_cast<float2*>(
                &out[(((size_t)bbB * H_ + head) * S_ + ssB) * HD_ + hd]) = vB;
        }
    }
}

// ===========================================================================
// Kernel 2: flash attention, fragment-order smem layouts.
// Block = 128 q-rows of one (b,h); 256 threads = 8 warps; warp w owns q-rows
// [w*16, w*16+16). Key chunks of 64. Softmax in log2 domain (ex2).
//
// Fragment-order layouts (lane = qr*4+qc, qr=lane>>2, qc=lane&3):
//  QF[wid][k8][lane] : uint4 = (Q[wq+qr][8k8+qc], Q[wq+qr+8][8k8+qc],
//                               Q[wq+qr][8k8+qc+4], Q[wq+qr+8][8k8+qc+4])
//  KF[k8][nt][lane]  : uint2 = (K[8nt+qr][8k8+qc], K[8nt+qr][8k8+qc+4])
//  VF[k8][nt][lane]  : uint2 = (V[8k8+qc][8nt+qr], V[8k8+qc+4][8nt+qr])
//  Ps[128][68]       : row-major P (q-major)
// smem = 8192 + 4096 + 4096 + 8704 words = 100352 B -> 2 CTAs/SM.
// ===========================================================================
#define LP 68
#define QF_WORDS 8192
#define KF_WORDS 4096
#define VF_WORDS 4096
#define ATT_SMEM ((size_t)(QF_WORDS + KF_WORDS + VF_WORDS + 128 * LP) * 4)

__global__ __launch_bounds__(256, 2) void attn_kernel(float* __restrict__ out)
{
    extern __shared__ uint32_t sma[];
    uint32_t* QF = sma;
    uint32_t* KF = sma + QF_WORDS;
    uint32_t* VF = KF + KF_WORDS;
    uint32_t* Ps = VF + VF_WORDS;

    const int tid  = threadIdx.x;
    const int wid  = tid >> 5;
    const int lane = tid & 31;
    const int qr = lane >> 2;
    const int qc = lane & 3;
    const int wq = wid * 16;                  // warp's q-row base

    const int qBase = blockIdx.x * 128;
    const int bh = blockIdx.y;
    const int b  = bh >> 4;
    const int h  = bh & 15;

    const float* qptr = g_q + (size_t)bh * S_ * HD_;
    const float* kptr = g_k + (size_t)bh * S_ * HD_;
    const float* vptr = g_v + (size_t)bh * S_ * HD_;

    // scale = 1/sqrt(64) * log2(e)  (softmax runs in log2 domain)
    const float QSC = 0.125f * 1.4426950408889634f;

    // --- Load Q tile [128][64] into fragment order (one-time) ---
    #pragma unroll
    for (int i = 0; i < 2; ++i) {
        int idx = tid + i * 256;              // 0..511
        int r = idx >> 2;                     // 0..127
        int cb = (idx & 3) << 4;              // 0,16,32,48
        const int widq = r >> 4;
        const int rm = r & 15;
        const int qrq = rm & 7;
        const int slr = rm >> 3;
        #pragma unroll
        for (int u = 0; u < 4; ++u) {
            float4 v = *reinterpret_cast<const float4*>(
                &qptr[(size_t)(qBase + r) * HD_ + cb + u * 4]);
            float vv[4] = {v.x, v.y, v.z, v.w};
            #pragma unroll
            for (int j = 0; j < 4; ++j) {
                int dd = cb + u * 4 + j;
                int k8 = dd >> 3, cm = dd & 7;
                int qcc = cm & 3, slc = cm >> 2;
                QF[(((widq * 8 + k8) * 32 + qrq * 4 + qcc) << 2) + slr + 2 * slc]
                    = f2tf32(vv[j] * QSC);
            }
        }
    }

    float o[8][4];
    #pragma unroll
    for (int nt = 0; nt < 8; ++nt)
        #pragma unroll
        for (int i = 0; i < 4; ++i) o[nt][i] = 0.f;
    float mA = -1e30f, mB = -1e30f, lA = 0.f, lB = 0.f;

    for (int kb = 0; kb < S_; kb += 64) {
        __syncthreads();   // prior QK reads of KF / PV reads of VF complete
        // --- Load K,V chunk [64][64] into fragment order ---
        #pragma unroll
        for (int i = 0; i < 4; ++i) {
            int id2 = tid + i * 256;          // 0..1023
            int rm = id2 & 7;                 // 0..7
            int c  = ((id2 >> 3) & 15) << 2;  // 0..60
            int g  = id2 >> 7;                // 0..7
            int r  = g * 8 + rm;              // key row 0..63
            float4 kv = *reinterpret_cast<const float4*>(
                &kptr[(size_t)(kb + r) * HD_ + c]);
            float kvv[4] = {kv.x, kv.y, kv.z, kv.w};
            float4 vv4 = *reinterpret_cast<const float4*>(
                &vptr[(size_t)(kb + r) * HD_ + c]);
            float vvv[4] = {vv4.x, vv4.y, vv4.z, vv4.w};
            #pragma unroll
            for (int j = 0; j < 4; ++j) {
                int dd = c + j;
                // K element (key r, d dd): nt=g, qr=rm; k8=dd>>3, qc/slot from dd
                {
                    int k8 = dd >> 3, cm = dd & 7;
                    int qcc = cm & 3, sl = cm >> 2;
                    KF[(((k8 * 8 + g) * 32 + rm * 4 + qcc) << 1) + sl]
                        = f2tf32(kvv[j]);
                }
                // V element (key r, d dd): k8=g, qc/slot from rm; nt=dd>>3, qr=dd&7
                {
                    int nt = dd >> 3;
                    int qrv = dd & 7;
                    int qcv = rm & 3, sl = rm >> 2;
                    VF[(((g * 8 + nt) * 32 + qrv * 4 + qcv) << 1) + sl]
                        = f2tf32(vvv[j]);
                }
            }
        }
        __syncthreads();

        // --- S = Q K^T : A = 1 LDS.128, B = 1 LDS.64 per fragment ---
        float s[8][4];
        #pragma unroll
        for (int nt = 0; nt < 8; ++nt)
            #pragma unroll
            for (int i = 0; i < 4; ++i) s[nt][i] = 0.f;

        #pragma unroll 2
        for (int k8 = 0; k8 < 8; ++k8) {
            uint4 av = *reinterpret_cast<const uint4*>(
                &QF[((wid * 8 + k8) * 32 + lane) << 2]);
            uint32_t a[4] = {av.x, av.y, av.z, av.w};
            #pragma unroll
            for (int nt = 0; nt < 8; ++nt) {
                uint2 bv = *reinterpret_cast<const uint2*>(
                    &KF[((k8 * 8 + nt) * 32 + lane) << 1]);
                uint32_t bfr[2] = {bv.x, bv.y};
                mma_tf32(s[nt], a, bfr, s[nt]);
            }
        }

        // --- Online softmax (log2 domain) on fragments ---
        float mtA = -1e30f, mtB = -1e30f;
        #pragma unroll
        for (int nt = 0; nt < 8; ++nt) {
            mtA = fmaxf(mtA, fmaxf(s[nt][0], s[nt][1]));
            mtB = fmaxf(mtB, fmaxf(s[nt][2], s[nt][3]));
        }
        #pragma unroll
        for (int off = 1; off < 4; off <<= 1) {
            mtA = fmaxf(mtA, __shfl_xor_sync(0xffffffffu, mtA, off));
            mtB = fmaxf(mtB, __shfl_xor_sync(0xffffffffu, mtB, off));
        }
        float mnA = fmaxf(mA, mtA), mnB = fmaxf(mB, mtB);
        float cA = ex2f(mA - mnA), cB = ex2f(mB - mnB);
        float rsA = 0.f, rsB = 0.f;
        #pragma unroll
        for (int nt = 0; nt < 8; ++nt) {
            s[nt][0] = ex2f(s[nt][0] - mnA);
            s[nt][1] = ex2f(s[nt][1] - mnA);
            s[nt][2] = ex2f(s[nt][2] - mnB);
            s[nt][3] = ex2f(s[nt][3] - mnB);
            rsA += s[nt][0] + s[nt][1];
            rsB += s[nt][2] + s[nt][3];
        }
        #pragma unroll
        for (int off = 1; off < 4; off <<= 1) {
            rsA += __shfl_xor_sync(0xffffffffu, rsA, off);
            rsB += __shfl_xor_sync(0xffffffffu, rsB, off);
        }
        lA = lA * cA + rsA;  mA = mnA;
        lB = lB * cB + rsB;  mB = mnB;
        #pragma unroll
        for (int nt = 0; nt < 8; ++nt) {
            o[nt][0] *= cA; o[nt][1] *= cA;
            o[nt][2] *= cB; o[nt][3] *= cB;
        }

        // --- Store P (tf32) to warp-private Ps rows ---
        #pragma unroll
        for (int nt = 0; nt < 8; ++nt) {
            uint2 pa = make_uint2(f2tf32(s[nt][0]), f2tf32(s[nt][1]));
            uint2 pb = make_uint2(f2tf32(s[nt][2]), f2tf32(s[nt][3]));
            *reinterpret_cast<uint2*>(&Ps[(wq + qr) * LP + nt * 8 + 2 * qc]) = pa;
            *reinterpret_cast<uint2*>(&Ps[(wq + qr + 8) * LP + nt * 8 + 2 * qc]) = pb;
        }
        __syncwarp();   // warp writes/reads its own 16 Ps rows only

        // --- O += P V : A scalar from Ps, B = 1 LDS.64 per fragment ---
        #pragma unroll 4
        for (int k8 = 0; k8 < 8; ++k8) {
            int k0 = k8 * 8;
            uint32_t a[4];
            a[0] = Ps[(wq + qr) * LP + k0 + qc];
            a[1] = Ps[(wq + qr + 8) * LP + k0 + qc];
            a[2] = Ps[(wq + qr) * LP + k0 + qc + 4];
            a[3] = Ps[(wq + qr + 8) * LP + k0 + qc + 4];
            #pragma unroll
            for (int nt = 0; nt < 8; ++nt) {
                uint2 bv = *reinterpret_cast<const uint2*>(
                    &VF[((k8 * 8 + nt) * 32 + lane) << 1]);
                uint32_t bfr[2] = {bv.x, bv.y};
                mma_tf32(o[nt], a, bfr, o[nt]);
            }
        }
    }

    // Epilogue: normalize, write [b,s,h*hd]
    float invA = 1.f / lA, invB = 1.f / lB;
    int rowA = qBase + wq + qr;
    int rowB = rowA + 8;
    #pragma unroll
    for (int nt = 0; nt < 8; ++nt) {
        int col = h * HD_ + nt * 8 + 2 * qc;
        float2 vA = make_float2(o[nt][0] * invA, o[nt][1] * invA);
        float2 vB = make_float2(o[nt][2] * invB, o[nt][3] * invB);
        *reinterpret_cast<float2*>(&out[(size_t)(b * S_ + rowA) * D_ + col]) = vA;
        *reinterpret_cast<float2*>(&out[(size_t)(b * S_ + rowB) * D_ + col]) = vB;
    }
}

// ---------------------------------------------------------------------------
extern "C" void kernel_launch(void* const* d_in, const int* in_sizes, int n_in,
                              void* d_out, int out_size)
{
    const float* x  = (const float*)d_in[0];
    const float* Wq = (const float*)d_in[1];
    const float* bq = (const float*)d_in[2];
    const float* Wk = (const float*)d_in[3];
    const float* bk = (const float*)d_in[4];
    const float* Wv = (const float*)d_in[5];
    const float* bv = (const float*)d_in[6];
    float* out = (float*)d_out;

    cudaFuncSetAttribute(qkv_mma_kernel,
                         cudaFuncAttributeMaxDynamicSharedMemorySize, (int)QKV_SMEM);
    qkv_mma_kernel<<<dim3(24, 64), 256, QKV_SMEM>>>(x, Wq, bq, Wk, bk, Wv, bv);

    cudaFuncSetAttribute(attn_kernel,
                         cudaFuncAttributeMaxDynamicSharedMemorySize, (int)ATT_SMEM);
    attn_kernel<<<dim3(S_ / 128, B_ * H_), 256, ATT_SMEM>>>(out);
}

// round 14
// speedup vs baseline: 1.9994x; 1.9994x over previous
#include <cuda_runtime.h>
#include <cuda_fp16.h>
#include <cstdint>
#include <math.h>

#define B_  4
#define S_  2048
#define D_  1024
#define H_  16
#define HD_ 64
#define M_  (B_ * S_)   // 8192

// Scratch for Q,K,V in [b,h,s,hd] layout, fp16 (Q pre-scaled by 0.125*log2e)
__device__ __half g_q[B_ * H_ * S_ * HD_];
__device__ __half g_k[B_ * H_ * S_ * HD_];
__device__ __half g_v[B_ * H_ * S_ * HD_];

// ---------------------------------------------------------------------------
// helpers
// ---------------------------------------------------------------------------
__device__ __forceinline__ uint32_t pack_f2h(float x, float y) {
    __half2 h = __floats2half2_rn(x, y);    // lo=x, hi=y
    return *reinterpret_cast<uint32_t*>(&h);
}
__device__ __forceinline__ float ex2f(float x) {
    float y;
    asm("ex2.approx.f32 %0, %1;" : "=f"(y) : "f"(x));
    return y;
}
__device__ __forceinline__ uint32_t prmt(uint32_t a, uint32_t b, uint32_t sel) {
    uint32_t r;
    asm("prmt.b32 %0, %1, %2, %3;" : "=r"(r) : "r"(a), "r"(b), "r"(sel));
    return r;
}
// fp16 MMA m16n8k16, f32 accumulate (portable sm_80+ PTX)
__device__ __forceinline__ void mma_f16(float d[4], const uint32_t a[4],
                                        const uint32_t b[2], const float c[4]) {
    asm volatile(
        "mma.sync.aligned.m16n8k16.row.col.f32.f16.f16.f32 "
        "{%0,%1,%2,%3}, {%4,%5,%6,%7}, {%8,%9}, {%10,%11,%12,%13};"
        : "=f"(d[0]), "=f"(d[1]), "=f"(d[2]), "=f"(d[3])
        : "r"(a[0]), "r"(a[1]), "r"(a[2]), "r"(a[3]),
          "r"(b[0]), "r"(b[1]),
          "f"(c[0]), "f"(c[1]), "f"(c[2]), "f"(c[3]));
}

// softmax scale folded into Q at projection time: 1/sqrt(64) * log2(e)
#define QSC_ (0.125f * 1.4426950408889634f)

// ===========================================================================
// Kernel 1: QKV projection via fp16 mma.sync (m16n8k16), double-buffered.
// CTA tile 128x128, BK=32 (32 chunks, 2 k16-steps each), 256 thr = 8 warps,
// warp tile 32x64. smem rows hold k-PAIRS as u32: [row][kp], LAP=20 (16+4).
// Output fp16 to g_q/g_k/g_v; Q scaled by QSC_.
// grid = (24, 64): bx>>3 = (q|k|v), (bx&7)*128 = n0, by*128 = m0.
// ===========================================================================
#define LAP 20
#define QSTG (2 * 128 * LAP)               // words per stage (A+B)
#define QKV_SMEM ((size_t)2 * QSTG * 4)    // 40960 B

__global__ __launch_bounds__(256, 2) void qkv_mma_kernel(
    const float* __restrict__ x,
    const float* __restrict__ Wq, const float* __restrict__ bq,
    const float* __restrict__ Wk, const float* __restrict__ bk,
    const float* __restrict__ Wv, const float* __restrict__ bv)
{
    extern __shared__ uint32_t smq[];

    const int tid  = threadIdx.x;
    const int lane = tid & 31;
    const int wid  = tid >> 5;
    const int qr = lane >> 2;
    const int qc = lane & 3;

    const int bx = blockIdx.x;
    const int z  = bx >> 3;
    const int n0 = (bx & 7) * 128;
    const int m0 = blockIdx.y * 128;

    const float* W    = (z == 0) ? Wq : (z == 1) ? Wk : Wv;
    const float* bias = (z == 0) ? bq : (z == 1) ? bk : bv;
    __half*      out  = (z == 0) ? g_q : (z == 1) ? g_k : g_v;
    const float  osc  = (z == 0) ? QSC_ : 1.0f;

    const int warpM = (wid >> 1) * 32;       // 0,32,64,96
    const int warpN = (wid & 1) * 64;        // 0,64

    const int lr = tid >> 3;                 // loader row 0..31 (x4 via i)
    const int lc = (tid & 7) << 2;           // loader f32 col 0,4..28
    const int lkp = lc >> 1;                 // k-pair col 0,2..14

    float acc[2][8][4];
    #pragma unroll
    for (int mt = 0; mt < 2; ++mt)
        #pragma unroll
        for (int nt = 0; nt < 8; ++nt)
            #pragma unroll
            for (int i = 0; i < 4; ++i) acc[mt][nt][i] = 0.f;

    float4 pa[4], pb[4];
    #pragma unroll
    for (int i = 0; i < 4; ++i) {
        int r = lr + i * 32;
        pa[i] = *reinterpret_cast<const float4*>(&x[(size_t)(m0 + r) * D_ + lc]);
        pb[i] = *reinterpret_cast<const float4*>(&W[(size_t)(n0 + r) * D_ + lc]);
    }
    {
        uint32_t* A = smq;
        uint32_t* Bp = smq + 128 * LAP;
        #pragma unroll
        for (int i = 0; i < 4; ++i) {
            int r = lr + i * 32;
            uint2 ta = make_uint2(pack_f2h(pa[i].x, pa[i].y), pack_f2h(pa[i].z, pa[i].w));
            *reinterpret_cast<uint2*>(&A[r * LAP + lkp]) = ta;
            uint2 tb = make_uint2(pack_f2h(pb[i].x, pb[i].y), pack_f2h(pb[i].z, pb[i].w));
            *reinterpret_cast<uint2*>(&Bp[r * LAP + lkp]) = tb;
        }
    }
    __syncthreads();

    for (int kc = 0; kc < 32; ++kc) {
        const int s = kc & 1;
        if (kc + 1 < 32) {
            int koff = (kc + 1) * 32;
            #pragma unroll
            for (int i = 0; i < 4; ++i) {
                int r = lr + i * 32;
                pa[i] = *reinterpret_cast<const float4*>(
                    &x[(size_t)(m0 + r) * D_ + koff + lc]);
                pb[i] = *reinterpret_cast<const float4*>(
                    &W[(size_t)(n0 + r) * D_ + koff + lc]);
            }
        }

        const uint32_t* As = smq + s * QSTG;
        const uint32_t* Bs = As + 128 * LAP;
        #pragma unroll
        for (int t = 0; t < 2; ++t) {
            int k0 = t * 8;                  // k-pair base
            uint32_t a[2][4];
            #pragma unroll
            for (int mt = 0; mt < 2; ++mt) {
                int r = warpM + mt * 16 + qr;
                a[mt][0] = As[r * LAP + k0 + qc];
                a[mt][1] = As[(r + 8) * LAP + k0 + qc];
                a[mt][2] = As[r * LAP + k0 + qc + 4];
                a[mt][3] = As[(r + 8) * LAP + k0 + qc + 4];
            }
            #pragma unroll
            for (int nt = 0; nt < 8; ++nt) {
                uint32_t b[2];
                int n = warpN + nt * 8 + qr;
                b[0] = Bs[n * LAP + k0 + qc];
                b[1] = Bs[n * LAP + k0 + qc + 4];
                mma_f16(acc[0][nt], a[0], b, acc[0][nt]);
                mma_f16(acc[1][nt], a[1], b, acc[1][nt]);
            }
        }

        if (kc + 1 < 32) {
            uint32_t* A = smq + (s ^ 1) * QSTG;
            uint32_t* Bp = A + 128 * LAP;
            #pragma unroll
            for (int i = 0; i < 4; ++i) {
                int r = lr + i * 32;
                uint2 ta = make_uint2(pack_f2h(pa[i].x, pa[i].y), pack_f2h(pa[i].z, pa[i].w));
                *reinterpret_cast<uint2*>(&A[r * LAP + lkp]) = ta;
                uint2 tb = make_uint2(pack_f2h(pb[i].x, pb[i].y), pack_f2h(pb[i].z, pb[i].w));
                *reinterpret_cast<uint2*>(&Bp[r * LAP + lkp]) = tb;
            }
        }
        __syncthreads();
    }

    // Epilogue: bias (+Q scale) -> fp16 pair -> STG.32 to [b,h,s,hd]
    #pragma unroll
    for (int mt = 0; mt < 2; ++mt) {
        #pragma unroll
        for (int nt = 0; nt < 8; ++nt) {
            int gn = n0 + warpN + nt * 8 + 2 * qc;   // even
            int head = gn >> 6;
            int hd = gn & 63;
            float b0 = bias[gn], b1 = bias[gn + 1];
            int rA = m0 + warpM + mt * 16 + qr;
            int rB = rA + 8;
            int bbA = rA >> 11, ssA = rA & (S_ - 1);
            int bbB = rB >> 11, ssB = rB & (S_ - 1);
            uint32_t pA = pack_f2h((acc[mt][nt][0] + b0) * osc,
                                   (acc[mt][nt][1] + b1) * osc);
            uint32_t pB = pack_f2h((acc[mt][nt][2] + b0) * osc,
                                   (acc[mt][nt][3] + b1) * osc);
            *reinterpret_cast<uint32_t*>(
                &out[(((size_t)bbA * H_ + head) * S_ + ssA) * HD_ + hd]) = pA;
            *reinterpret_cast<uint32_t*>(
                &out[(((size_t)bbB * H_ + head) * S_ + ssB) * HD_ + hd]) = pB;
        }
    }
}

// ===========================================================================
// Kernel 2: flash attention via fp16 mma.sync (m16n8k16).
// Block = 128 q-rows of one (b,h); 256 threads = 8 warps; warp w owns q-rows
// [w*16, w*16+16). Key chunks of 64 -> 4 k16 steps in QK and PV.
// smem layouts (u32 = fp16 pair), row pad to 36:
//   Qs[128][36]  rows=q, cols=d-pairs     (direct LDG.128->STS.128 copy)
//   Ks[64][36]   rows=key, cols=d-pairs   (direct copy)
//   VsT[64][36]  rows=d, cols=KEY-pairs   (prmt transpose, bank=lane stores)
//   Ps[128][36]  rows=q, cols=key-pairs
// smem = (4608+2304+2304+4608)*4 = 55296 B -> 2 CTAs/SM (regs are the cap).
// ===========================================================================
#define LQP 36
#define ATT_SMEM ((size_t)(128 * LQP + 64 * LQP + 64 * LQP + 128 * LQP) * 4)

__global__ __launch_bounds__(256, 2) void attn_kernel(float* __restrict__ out)
{
    extern __shared__ uint32_t sma[];
    uint32_t* Qs  = sma;                      // [128][36]
    uint32_t* Ks  = Qs + 128 * LQP;           // [64][36]
    uint32_t* VsT = Ks + 64 * LQP;            // [64][36]
    uint32_t* Ps  = VsT + 64 * LQP;           // [128][36]

    const int tid  = threadIdx.x;
    const int wid  = tid >> 5;
    const int lane = tid & 31;
    const int qr = lane >> 2;
    const int qc = lane & 3;
    const int wq = wid * 16;                  // warp's q-row base

    const int qBase = blockIdx.x * 128;
    const int bh = blockIdx.y;
    const int b  = bh >> 4;
    const int h  = bh & 15;

    const __half* qptr = g_q + (size_t)bh * S_ * HD_;
    const __half* kptr = g_k + (size_t)bh * S_ * HD_;
    const __half* vptr = g_v + (size_t)bh * S_ * HD_;

    // --- Load Q tile [128][64]h: straight uint4 copy (already packed pairs) ---
    #pragma unroll
    for (int i = 0; i < 4; ++i) {
        int id = tid + i * 256;               // 0..1023
        int r  = id >> 3;                     // 0..127
        int c4 = id & 7;                      // uint4 index (8 halves each)
        uint4 v = *reinterpret_cast<const uint4*>(
            &qptr[(size_t)(qBase + r) * HD_ + c4 * 8]);
        *reinterpret_cast<uint4*>(&Qs[r * LQP + c4 * 4]) = v;
    }

    float o[8][4];
    #pragma unroll
    for (int nt = 0; nt < 8; ++nt)
        #pragma unroll
        for (int i = 0; i < 4; ++i) o[nt][i] = 0.f;
    float mA = -1e30f, mB = -1e30f, lA = 0.f, lB = 0.f;

    for (int kb = 0; kb < S_; kb += 64) {
        __syncthreads();   // prior QK reads of Ks / PV reads of VsT complete
        // --- K chunk [64][64]h: straight copy ---
        #pragma unroll
        for (int i = 0; i < 2; ++i) {
            int id = tid + i * 256;           // 0..511
            int r  = id >> 3;                 // 0..63
            int c4 = id & 7;
            uint4 v = *reinterpret_cast<const uint4*>(
                &kptr[(size_t)(kb + r) * HD_ + c4 * 8]);
            *reinterpret_cast<uint4*>(&Ks[r * LQP + c4 * 4]) = v;
        }
        // --- V chunk: transpose to key-pair-major via prmt ---
        {
            int u  = tid & 31;                // key pair 0..31
            int db = tid >> 5;                // d block 0..7 (8 d per block)
            uint4 va = *reinterpret_cast<const uint4*>(
                &vptr[(size_t)(kb + 2 * u) * HD_ + db * 8]);
            uint4 vb = *reinterpret_cast<const uint4*>(
                &vptr[(size_t)(kb + 2 * u + 1) * HD_ + db * 8]);
            uint32_t aw[4] = {va.x, va.y, va.z, va.w};
            uint32_t bw[4] = {vb.x, vb.y, vb.z, vb.w};
            #pragma unroll
            for (int j = 0; j < 4; ++j) {
                // aw[j] = (keyA dBase+2j, keyA dBase+2j+1); bw[j] same for keyB
                VsT[(db * 8 + 2 * j + 0) * LQP + u] = prmt(aw[j], bw[j], 0x5410);
                VsT[(db * 8 + 2 * j + 1) * LQP + u] = prmt(aw[j], bw[j], 0x7632);
            }
        }
        __syncthreads();

        // --- S = Q K^T : 4 k16 steps, 8 n-tiles per warp ---
        float s[8][4];
        #pragma unroll
        for (int nt = 0; nt < 8; ++nt)
            #pragma unroll
            for (int i = 0; i < 4; ++i) s[nt][i] = 0.f;

        #pragma unroll
        for (int t = 0; t < 4; ++t) {
            int k0 = t * 8;                   // k-pair base (16 d values)
            uint32_t a[4];
            a[0] = Qs[(wq + qr) * LQP + k0 + qc];
            a[1] = Qs[(wq + qr + 8) * LQP + k0 + qc];
            a[2] = Qs[(wq + qr) * LQP + k0 + qc + 4];
            a[3] = Qs[(wq + qr + 8) * LQP + k0 + qc + 4];
            #pragma unroll
            for (int nt = 0; nt < 8; ++nt) {
                uint32_t bfr[2];
                bfr[0] = Ks[(nt * 8 + qr) * LQP + k0 + qc];
                bfr[1] = Ks[(nt * 8 + qr) * LQP + k0 + qc + 4];
                mma_f16(s[nt], a, bfr, s[nt]);
            }
        }

        // --- Online softmax (log2 domain; Q pre-scaled by 0.125*log2e) ---
        float mtA = -1e30f, mtB = -1e30f;
        #pragma unroll
        for (int nt = 0; nt < 8; ++nt) {
            mtA = fmaxf(mtA, fmaxf(s[nt][0], s[nt][1]));
            mtB = fmaxf(mtB, fmaxf(s[nt][2], s[nt][3]));
        }
        #pragma unroll
        for (int off = 1; off < 4; off <<= 1) {
            mtA = fmaxf(mtA, __shfl_xor_sync(0xffffffffu, mtA, off));
            mtB = fmaxf(mtB, __shfl_xor_sync(0xffffffffu, mtB, off));
        }
        float mnA = fmaxf(mA, mtA), mnB = fmaxf(mB, mtB);
        float cA = ex2f(mA - mnA), cB = ex2f(mB - mnB);
        float rsA = 0.f, rsB = 0.f;
        #pragma unroll
        for (int nt = 0; nt < 8; ++nt) {
            s[nt][0] = ex2f(s[nt][0] - mnA);
            s[nt][1] = ex2f(s[nt][1] - mnA);
            s[nt][2] = ex2f(s[nt][2] - mnB);
            s[nt][3] = ex2f(s[nt][3] - mnB);
            rsA += s[nt][0] + s[nt][1];
            rsB += s[nt][2] + s[nt][3];
        }
        #pragma unroll
        for (int off = 1; off < 4; off <<= 1) {
            rsA += __shfl_xor_sync(0xffffffffu, rsA, off);
            rsB += __shfl_xor_sync(0xffffffffu, rsB, off);
        }
        lA = lA * cA + rsA;  mA = mnA;
        lB = lB * cB + rsB;  mB = mnB;
        #pragma unroll
        for (int nt = 0; nt < 8; ++nt) {
            o[nt][0] *= cA; o[nt][1] *= cA;
            o[nt][2] *= cB; o[nt][3] *= cB;
        }

        // --- Store P as fp16 pairs (cols nt*8+2qc,+1 -> kp = nt*4+qc) ---
        #pragma unroll
        for (int nt = 0; nt < 8; ++nt) {
            Ps[(wq + qr) * LQP + nt * 4 + qc]     = pack_f2h(s[nt][0], s[nt][1]);
            Ps[(wq + qr + 8) * LQP + nt * 4 + qc] = pack_f2h(s[nt][2], s[nt][3]);
        }
        __syncwarp();   // warp writes/reads its own 16 Ps rows only

        // --- O += P V : 4 k16 steps over 64 keys ---
        #pragma unroll
        for (int t = 0; t < 4; ++t) {
            int k0 = t * 8;                   // key-pair base
            uint32_t a[4];
            a[0] = Ps[(wq + qr) * LQP + k0 + qc];
            a[1] = Ps[(wq + qr + 8) * LQP + k0 + qc];
            a[2] = Ps[(wq + qr) * LQP + k0 + qc + 4];
            a[3] = Ps[(wq + qr + 8) * LQP + k0 + qc + 4];
            #pragma unroll
            for (int nt = 0; nt < 8; ++nt) {
                uint32_t bfr[2];
                bfr[0] = VsT[(nt * 8 + qr) * LQP + k0 + qc];
                bfr[1] = VsT[(nt * 8 + qr) * LQP + k0 + qc + 4];
                mma_f16(o[nt], a, bfr, o[nt]);
            }
        }
    }

    // Epilogue: normalize, write f32 [b,s,h*hd]
    float invA = 1.f / lA, invB = 1.f / lB;
    int rowA = qBase + wq + qr;
    int rowB = rowA + 8;
    #pragma unroll
    for (int nt = 0; nt < 8; ++nt) {
        int col = h * HD_ + nt * 8 + 2 * qc;
        float2 vA = make_float2(o[nt][0] * invA, o[nt][1] * invA);
        float2 vB = make_float2(o[nt][2] * invB, o[nt][3] * invB);
        *reinterpret_cast<float2*>(&out[(size_t)(b * S_ + rowA) * D_ + col]) = vA;
        *reinterpret_cast<float2*>(&out[(size_t)(b * S_ + rowB) * D_ + col]) = vB;
    }
}

// ---------------------------------------------------------------------------
extern "C" void kernel_launch(void* const* d_in, const int* in_sizes, int n_in,
                              void* d_out, int out_size)
{
    const float* x  = (const float*)d_in[0];
    const float* Wq = (const float*)d_in[1];
    const float* bq = (const float*)d_in[2];
    const float* Wk = (const float*)d_in[3];
    const float* bk = (const float*)d_in[4];
    const float* Wv = (const float*)d_in[5];
    const float* bv = (const float*)d_in[6];
    float* out = (float*)d_out;

    cudaFuncSetAttribute(qkv_mma_kernel,
                         cudaFuncAttributeMaxDynamicSharedMemorySize, (int)QKV_SMEM);
    qkv_mma_kernel<<<dim3(24, 64), 256, QKV_SMEM>>>(x, Wq, bq, Wk, bk, Wv, bv);

    cudaFuncSetAttribute(attn_kernel,
                         cudaFuncAttributeMaxDynamicSharedMemorySize, (int)ATT_SMEM);
    attn_kernel<<<dim3(S_ / 128, B_ * H_), 256, ATT_SMEM>>>(out);
}

// round 15
// speedup vs baseline: 2.4857x; 1.2432x over previous
#include <cuda_runtime.h>
#include <cuda_fp16.h>
#include <cstdint>
#include <math.h>

#define B_  4
#define S_  2048
#define D_  1024
#define H_  16
#define HD_ 64
#define M_  (B_ * S_)   // 8192

// Scratch for Q,K,V in [b,h,s,hd] layout, fp16 (Q pre-scaled by 0.125*log2e)
__device__ __half g_q[B_ * H_ * S_ * HD_];
__device__ __half g_k[B_ * H_ * S_ * HD_];
__device__ __half g_v[B_ * H_ * S_ * HD_];

// ---------------------------------------------------------------------------
// helpers
// ---------------------------------------------------------------------------
__device__ __forceinline__ uint32_t pack_f2h(float x, float y) {
    __half2 h = __floats2half2_rn(x, y);
    return *reinterpret_cast<uint32_t*>(&h);
}
__device__ __forceinline__ float ex2f(float x) {
    float y;
    asm("ex2.approx.f32 %0, %1;" : "=f"(y) : "f"(x));
    return y;
}
__device__ __forceinline__ uint32_t cvta_smem(const void* p) {
    uint32_t a;
    asm("{ .reg .u64 t; cvta.to.shared.u64 t, %1; cvt.u32.u64 %0, t; }"
        : "=r"(a) : "l"(p));
    return a;
}
__device__ __forceinline__ void ldsm4(uint32_t r[4], uint32_t a) {
    asm volatile("ldmatrix.sync.aligned.m8n8.x4.shared.b16 {%0,%1,%2,%3}, [%4];"
        : "=r"(r[0]), "=r"(r[1]), "=r"(r[2]), "=r"(r[3]) : "r"(a));
}
__device__ __forceinline__ void ldsm4t(uint32_t r[4], uint32_t a) {
    asm volatile("ldmatrix.sync.aligned.m8n8.x4.trans.shared.b16 {%0,%1,%2,%3}, [%4];"
        : "=r"(r[0]), "=r"(r[1]), "=r"(r[2]), "=r"(r[3]) : "r"(a));
}
__device__ __forceinline__ void cp_async16(uint32_t s, const void* g) {
    asm volatile("cp.async.ca.shared.global [%0], [%1], 16;"
        :: "r"(s), "l"(g) : "memory");
}
#define CP_COMMIT() asm volatile("cp.async.commit_group;" ::: "memory")
#define CP_WAIT0()  asm volatile("cp.async.wait_group 0;" ::: "memory")

// fp16 MMA m16n8k16, f32 accumulate
__device__ __forceinline__ void mma_f16(float d[4], const uint32_t a[4],
                                        const uint32_t b[2], const float c[4]) {
    asm volatile(
        "mma.sync.aligned.m16n8k16.row.col.f32.f16.f16.f32 "
        "{%0,%1,%2,%3}, {%4,%5,%6,%7}, {%8,%9}, {%10,%11,%12,%13};"
        : "=f"(d[0]), "=f"(d[1]), "=f"(d[2]), "=f"(d[3])
        : "r"(a[0]), "r"(a[1]), "r"(a[2]), "r"(a[3]),
          "r"(b[0]), "r"(b[1]),
          "f"(c[0]), "f"(c[1]), "f"(c[2]), "f"(c[3]));
}

#define QSC_ (0.125f * 1.4426950408889634f)

// ===========================================================================
// Kernel 1: QKV projection, fp16 mma.sync + ldmatrix fragments.
// CTA tile 128x128, BK=32, 256 thr = 8 warps (4x2), warp tile 32x64.
// smem rows hold k-pairs as u32, LAP=20 (bank-complete for ldmatrix).
// ===========================================================================
#define LAP 20
#define QSTG (2 * 128 * LAP)               // words per stage (A+B)
#define QKV_SMEM ((size_t)2 * QSTG * 4)    // 40960 B

__global__ __launch_bounds__(256, 2) void qkv_mma_kernel(
    const float* __restrict__ x,
    const float* __restrict__ Wq, const float* __restrict__ bq,
    const float* __restrict__ Wk, const float* __restrict__ bk,
    const float* __restrict__ Wv, const float* __restrict__ bv)
{
    extern __shared__ uint32_t smq[];
    const uint32_t smqB = cvta_smem(smq);

    const int tid  = threadIdx.x;
    const int lane = tid & 31;
    const int wid  = tid >> 5;
    const int qr = lane >> 2;
    const int qc = lane & 3;
    const int ln7 = lane & 7;
    const int tI  = lane >> 3;

    const int bx = blockIdx.x;
    const int z  = bx >> 3;
    const int n0 = (bx & 7) * 128;
    const int m0 = blockIdx.y * 128;

    const float* W    = (z == 0) ? Wq : (z == 1) ? Wk : Wv;
    const float* bias = (z == 0) ? bq : (z == 1) ? bk : bv;
    __half*      out  = (z == 0) ? g_q : (z == 1) ? g_k : g_v;
    const float  osc  = (z == 0) ? QSC_ : 1.0f;

    const int warpM = (wid >> 1) * 32;
    const int warpN = (wid & 1) * 64;

    const int lr = tid >> 3;
    const int lc = (tid & 7) << 2;
    const int lkp = lc >> 1;

    // ldmatrix fragment base addresses (bytes)
    const uint32_t aAddr = smqB +
        (((warpM + (lane & 15)) * LAP + ((lane >> 4) << 2)) << 2);
    const uint32_t bAddr = smqB +
        (((128 * LAP) + (warpN + 8 * (tI >> 1) + ln7) * LAP + (tI & 1) * 4) << 2);
    const uint32_t SOFF = (uint32_t)QSTG << 2;   // stage byte stride

    float acc[2][8][4];
    #pragma unroll
    for (int mt = 0; mt < 2; ++mt)
        #pragma unroll
        for (int nt = 0; nt < 8; ++nt)
            #pragma unroll
            for (int i = 0; i < 4; ++i) acc[mt][nt][i] = 0.f;

    float4 pa[4], pb[4];
    #pragma unroll
    for (int i = 0; i < 4; ++i) {
        int r = lr + i * 32;
        pa[i] = *reinterpret_cast<const float4*>(&x[(size_t)(m0 + r) * D_ + lc]);
        pb[i] = *reinterpret_cast<const float4*>(&W[(size_t)(n0 + r) * D_ + lc]);
    }
    {
        uint32_t* A = smq;
        uint32_t* Bp = smq + 128 * LAP;
        #pragma unroll
        for (int i = 0; i < 4; ++i) {
            int r = lr + i * 32;
            uint2 ta = make_uint2(pack_f2h(pa[i].x, pa[i].y), pack_f2h(pa[i].z, pa[i].w));
            *reinterpret_cast<uint2*>(&A[r * LAP + lkp]) = ta;
            uint2 tb = make_uint2(pack_f2h(pb[i].x, pb[i].y), pack_f2h(pb[i].z, pb[i].w));
            *reinterpret_cast<uint2*>(&Bp[r * LAP + lkp]) = tb;
        }
    }
    __syncthreads();

    for (int kc = 0; kc < 32; ++kc) {
        const int stg = kc & 1;
        if (kc + 1 < 32) {
            int koff = (kc + 1) * 32;
            #pragma unroll
            for (int i = 0; i < 4; ++i) {
                int r = lr + i * 32;
                pa[i] = *reinterpret_cast<const float4*>(
                    &x[(size_t)(m0 + r) * D_ + koff + lc]);
                pb[i] = *reinterpret_cast<const float4*>(
                    &W[(size_t)(n0 + r) * D_ + koff + lc]);
            }
        }

        const uint32_t sO = stg * SOFF;
        #pragma unroll
        for (int t = 0; t < 2; ++t) {
            uint32_t a0[4], a1[4];
            ldsm4(a0, aAddr + sO + t * 32);
            ldsm4(a1, aAddr + sO + t * 32 + 16 * LAP * 4);
            #pragma unroll
            for (int j = 0; j < 4; ++j) {
                uint32_t bb[4];
                ldsm4(bb, bAddr + sO + j * (16 * LAP * 4) + t * 32);
                mma_f16(acc[0][2 * j],     a0, bb,     acc[0][2 * j]);
                mma_f16(acc[0][2 * j + 1], a0, bb + 2, acc[0][2 * j + 1]);
                mma_f16(acc[1][2 * j],     a1, bb,     acc[1][2 * j]);
                mma_f16(acc[1][2 * j + 1], a1, bb + 2, acc[1][2 * j + 1]);
            }
        }

        if (kc + 1 < 32) {
            uint32_t* A = smq + (stg ^ 1) * QSTG;
            uint32_t* Bp = A + 128 * LAP;
            #pragma unroll
            for (int i = 0; i < 4; ++i) {
                int r = lr + i * 32;
                uint2 ta = make_uint2(pack_f2h(pa[i].x, pa[i].y), pack_f2h(pa[i].z, pa[i].w));
                *reinterpret_cast<uint2*>(&A[r * LAP + lkp]) = ta;
                uint2 tb = make_uint2(pack_f2h(pb[i].x, pb[i].y), pack_f2h(pb[i].z, pb[i].w));
                *reinterpret_cast<uint2*>(&Bp[r * LAP + lkp]) = tb;
            }
        }
        __syncthreads();
    }

    // Epilogue: bias (+Q scale) -> fp16 pair -> STG.32 to [b,h,s,hd]
    #pragma unroll
    for (int mt = 0; mt < 2; ++mt) {
        #pragma unroll
        for (int nt = 0; nt < 8; ++nt) {
            int gn = n0 + warpN + nt * 8 + 2 * qc;
            int head = gn >> 6;
            int hd = gn & 63;
            float b0 = bias[gn], b1 = bias[gn + 1];
            int rA = m0 + warpM + mt * 16 + qr;
            int rB = rA + 8;
            int bbA = rA >> 11, ssA = rA & (S_ - 1);
            int bbB = rB >> 11, ssB = rB & (S_ - 1);
            uint32_t pA = pack_f2h((acc[mt][nt][0] + b0) * osc,
                                   (acc[mt][nt][1] + b1) * osc);
            uint32_t pB = pack_f2h((acc[mt][nt][2] + b0) * osc,
                                   (acc[mt][nt][3] + b1) * osc);
            *reinterpret_cast<uint32_t*>(
                &out[(((size_t)bbA * H_ + head) * S_ + ssA) * HD_ + hd]) = pA;
            *reinterpret_cast<uint32_t*>(
                &out[(((size_t)bbB * H_ + head) * S_ + ssB) * HD_ + hd]) = pB;
        }
    }
}

// ===========================================================================
// Kernel 2: flash attention, fp16 mma.sync + ldmatrix + cp.async pipeline.
// Block = 128 q-rows of one (b,h); 256 threads = 8 warps.
// Key chunks of 64, K/V double-buffered via cp.async (natural layout);
// V read with ldmatrix.trans (no transpose on store).
// smem u32 words (LQP=36 pad -> ldmatrix bank-complete):
//   Qs[128][36] | Ks[2][64][36] | Vs[2][64][36] | Ps[128][36]
//   = 18432 words = 73728 B -> 2 CTAs/SM.
// ===========================================================================
#define LQP 36
#define QS_OFF 0
#define KS_OFF (128 * LQP)                 // 4608
#define VS_OFF (KS_OFF + 2 * 64 * LQP)     // 9216
#define PS_OFF (VS_OFF + 2 * 64 * LQP)     // 13824
#define ATT_SMEM ((size_t)(PS_OFF + 128 * LQP) * 4)   // 73728 B
#define KVSTG ((uint32_t)(64 * LQP) << 2)  // stage byte stride

__global__ __launch_bounds__(256, 2) void attn_kernel(float* __restrict__ out)
{
    extern __shared__ uint32_t sma[];
    const uint32_t smaB = cvta_smem(sma);

    const int tid  = threadIdx.x;
    const int wid  = tid >> 5;
    const int lane = tid & 31;
    const int qr = lane >> 2;
    const int qc = lane & 3;
    const int ln7 = lane & 7;
    const int tI  = lane >> 3;
    const int wq = wid * 16;

    const int qBase = blockIdx.x * 128;
    const int bh = blockIdx.y;
    const int b  = bh >> 4;
    const int h  = bh & 15;

    const __half* qptr = g_q + (size_t)bh * S_ * HD_;
    const __half* kptr = g_k + (size_t)bh * S_ * HD_;
    const __half* vptr = g_v + (size_t)bh * S_ * HD_;

    // --- prefetch K/V chunk 0 into stage 0 (cp.async) ---
    #pragma unroll
    for (int i = 0; i < 2; ++i) {
        int idx = tid + i * 256;           // 0..511
        int r = idx >> 3, sg = idx & 7;
        cp_async16(smaB + ((KS_OFF + r * LQP + sg * 4) << 2), kptr + r * HD_ + sg * 8);
        cp_async16(smaB + ((VS_OFF + r * LQP + sg * 4) << 2), vptr + r * HD_ + sg * 8);
    }
    CP_COMMIT();

    // --- Q tile [128][64]h: straight uint4 copy ---
    uint32_t* Qs = sma + QS_OFF;
    #pragma unroll
    for (int i = 0; i < 4; ++i) {
        int id = tid + i * 256;
        int r  = id >> 3;
        int c4 = id & 7;
        uint4 v = *reinterpret_cast<const uint4*>(
            &qptr[(size_t)(qBase + r) * HD_ + c4 * 8]);
        *reinterpret_cast<uint4*>(&Qs[r * LQP + c4 * 4]) = v;
    }

    // ldmatrix fragment base addresses (bytes)
    const uint32_t qA = smaB + (((wq + (lane & 15)) * LQP + ((lane >> 4) << 2)) << 2);
    const uint32_t pA = smaB + ((PS_OFF + (wq + (lane & 15)) * LQP + ((lane >> 4) << 2)) << 2);
    const uint32_t kB0 = smaB + ((KS_OFF + (8 * (tI >> 1) + ln7) * LQP + (tI & 1) * 4) << 2);
    const uint32_t vB0 = smaB + ((VS_OFF + ((tI & 1) * 8 + ln7) * LQP + (tI >> 1) * 4) << 2);
    uint32_t* Ps = sma + PS_OFF;

    float o[8][4];
    #pragma unroll
    for (int nt = 0; nt < 8; ++nt)
        #pragma unroll
        for (int i = 0; i < 4; ++i) o[nt][i] = 0.f;
    float mA = -1e30f, mB = -1e30f, lA = 0.f, lB = 0.f;

    CP_WAIT0();
    __syncthreads();

    for (int kb = 0; kb < S_; kb += 64) {
        const int stg = (kb >> 6) & 1;
        // prefetch next chunk into the other stage
        if (kb + 64 < S_) {
            const __half* kp = kptr + (size_t)(kb + 64) * HD_;
            const __half* vp = vptr + (size_t)(kb + 64) * HD_;
            uint32_t dK = smaB + ((KS_OFF + (stg ^ 1) * (64 * LQP)) << 2);
            uint32_t dV = smaB + ((VS_OFF + (stg ^ 1) * (64 * LQP)) << 2);
            #pragma unroll
            for (int i = 0; i < 2; ++i) {
                int idx = tid + i * 256;
                int r = idx >> 3, sg = idx & 7;
                cp_async16(dK + ((r * LQP + sg * 4) << 2), kp + r * HD_ + sg * 8);
                cp_async16(dV + ((r * LQP + sg * 4) << 2), vp + r * HD_ + sg * 8);
            }
            CP_COMMIT();
        }

        // --- S = Q K^T : ldmatrix fragments ---
        float s8[8][4];
        #pragma unroll
        for (int nt = 0; nt < 8; ++nt)
            #pragma unroll
            for (int i = 0; i < 4; ++i) s8[nt][i] = 0.f;

        const uint32_t kB = kB0 + stg * KVSTG;
        #pragma unroll
        for (int t = 0; t < 4; ++t) {
            uint32_t a[4];
            ldsm4(a, qA + t * 32);
            #pragma unroll
            for (int j = 0; j < 4; ++j) {
                uint32_t bb[4];
                ldsm4(bb, kB + j * (16 * LQP * 4) + t * 32);
                mma_f16(s8[2 * j],     a, bb,     s8[2 * j]);
                mma_f16(s8[2 * j + 1], a, bb + 2, s8[2 * j + 1]);
            }
        }

        // --- Online softmax (log2 domain) ---
        float mtA = -1e30f, mtB = -1e30f;
        #pragma unroll
        for (int nt = 0; nt < 8; ++nt) {
            mtA = fmaxf(mtA, fmaxf(s8[nt][0], s8[nt][1]));
            mtB = fmaxf(mtB, fmaxf(s8[nt][2], s8[nt][3]));
        }
        #pragma unroll
        for (int off = 1; off < 4; off <<= 1) {
            mtA = fmaxf(mtA, __shfl_xor_sync(0xffffffffu, mtA, off));
            mtB = fmaxf(mtB, __shfl_xor_sync(0xffffffffu, mtB, off));
        }
        float mnA = fmaxf(mA, mtA), mnB = fmaxf(mB, mtB);
        float cA = ex2f(mA - mnA), cB = ex2f(mB - mnB);
        float rsA = 0.f, rsB = 0.f;
        #pragma unroll
        for (int nt = 0; nt < 8; ++nt) {
            s8[nt][0] = ex2f(s8[nt][0] - mnA);
            s8[nt][1] = ex2f(s8[nt][1] - mnA);
            s8[nt][2] = ex2f(s8[nt][2] - mnB);
            s8[nt][3] = ex2f(s8[nt][3] - mnB);
            rsA += s8[nt][0] + s8[nt][1];
            rsB += s8[nt][2] + s8[nt][3];
        }
        #pragma unroll
        for (int off = 1; off < 4; off <<= 1) {
            rsA += __shfl_xor_sync(0xffffffffu, rsA, off);
            rsB += __shfl_xor_sync(0xffffffffu, rsB, off);
        }
        lA = lA * cA + rsA;  mA = mnA;
        lB = lB * cB + rsB;  mB = mnB;
        #pragma unroll
        for (int nt = 0; nt < 8; ++nt) {
            o[nt][0] *= cA; o[nt][1] *= cA;
            o[nt][2] *= cB; o[nt][3] *= cB;
        }

        // --- Store P as fp16 pairs (warp-private rows) ---
        #pragma unroll
        for (int nt = 0; nt < 8; ++nt) {
            Ps[(wq + qr) * LQP + nt * 4 + qc]     = pack_f2h(s8[nt][0], s8[nt][1]);
            Ps[(wq + qr + 8) * LQP + nt * 4 + qc] = pack_f2h(s8[nt][2], s8[nt][3]);
        }
        __syncwarp();

        // --- O += P V : ldmatrix A (Ps) + ldmatrix.trans B (natural V) ---
        const uint32_t vB = vB0 + stg * KVSTG;
        #pragma unroll
        for (int t = 0; t < 4; ++t) {
            uint32_t a[4];
            ldsm4(a, pA + t * 32);
            #pragma unroll
            for (int j = 0; j < 4; ++j) {
                uint32_t bb[4];
                ldsm4t(bb, vB + t * (16 * LQP * 4) + j * 32);
                mma_f16(o[2 * j],     a, bb,     o[2 * j]);
                mma_f16(o[2 * j + 1], a, bb + 2, o[2 * j + 1]);
            }
        }

        if (kb + 64 < S_) CP_WAIT0();
        __syncthreads();
    }

    // Epilogue: normalize, write f32 [b,s,h*hd]
    float invA = 1.f / lA, invB = 1.f / lB;
    int rowA = qBase + wq + qr;
    int rowB = rowA + 8;
    #pragma unroll
    for (int nt = 0; nt < 8; ++nt) {
        int col = h * HD_ + nt * 8 + 2 * qc;
        float2 vA = make_float2(o[nt][0] * invA, o[nt][1] * invA);
        float2 vB2 = make_float2(o[nt][2] * invB, o[nt][3] * invB);
        *reinterpret_cast<float2*>(&out[(size_t)(b * S_ + rowA) * D_ + col]) = vA;
        *reinterpret_cast<float2*>(&out[(size_t)(b * S_ + rowB) * D_ + col]) = vB2;
    }
}

// ---------------------------------------------------------------------------
extern "C" void kernel_launch(void* const* d_in, const int* in_sizes, int n_in,
                              void* d_out, int out_size)
{
    const float* x  = (const float*)d_in[0];
    const float* Wq = (const float*)d_in[1];
    const float* bq = (const float*)d_in[2];
    const float* Wk = (const float*)d_in[3];
    const float* bk = (const float*)d_in[4];
    const float* Wv = (const float*)d_in[5];
    const float* bv = (const float*)d_in[6];
    float* out = (float*)d_out;

    cudaFuncSetAttribute(qkv_mma_kernel,
                         cudaFuncAttributeMaxDynamicSharedMemorySize, (int)QKV_SMEM);
    qkv_mma_kernel<<<dim3(24, 64), 256, QKV_SMEM>>>(x, Wq, bq, Wk, bk, Wv, bv);

    cudaFuncSetAttribute(attn_kernel,
                         cudaFuncAttributeMaxDynamicSharedMemorySize, (int)ATT_SMEM);
    attn_kernel<<<dim3(S_ / 128, B_ * H_), 256, ATT_SMEM>>>(out);
}